// round 12
// baseline (speedup 1.0000x reference)
#include <cuda_runtime.h>

// T=2048, B=1024, H=50, 4H=200. Only batch row B-1 reaches the output
// (reference takes hs[:, -1, :] on the batch axis) and the recurrence is
// batch-independent -> single length-2048 sequence, H=50, on ONE SM.
#define TT 2048
#define BB 1024
#define HH 50
#define NTHREADS 128   // 4 warps, 1 per SMSP; lane pair 2u/2u+1 owns unit u

// Per-timestep hidden history; output dot handled in parallel epilogue.
__device__ float g_hs[TT * HH];

typedef unsigned long long ull;

__device__ __forceinline__ ull ffma2(ull a, ull b, ull c) {
    ull d;
    asm("fma.rn.f32x2 %0, %1, %2, %3;" : "=l"(d) : "l"(a), "l"(b), "l"(c));
    return d;
}
__device__ __forceinline__ float tanh_fast(float x) {
    float r;
    asm("tanh.approx.f32 %0, %1;" : "=f"(r) : "f"(x));
    return r;
}

__global__ __launch_bounds__(NTHREADS, 1)
void lstm_seq_kernel(const float* __restrict__ x,      // (T, B, 1)
                     const float* __restrict__ W_ih,   // (4H, 1)
                     const float* __restrict__ W_hh,   // (4H, H)
                     const float* __restrict__ b_ih,
                     const float* __restrict__ b_hh,
                     const float* __restrict__ W_lin,  // (1, H)
                     const float* __restrict__ b_lin,
                     float* __restrict__ out)          // T floats
{
    __shared__ __align__(16) float h_s[2][56];  // double buffer
    __shared__ float xcol[TT];

    const int j    = threadIdx.x;
    const int half = j & 1;                 // 0: gates (i,g)   1: gates (f,o)
    const int u    = j >> 1;                // unit 0..63 (>=50 redundant)
    const int uc   = (u < HH) ? u : (HH - 1);
    // rowA: i (even) / f (odd) -- always sigmoid
    // rowB: g (even, tanh) / o (odd, sigmoid)
    const int rowA = half ? (HH + uc)     : uc;
    const int rowB = half ? (3 * HH + uc) : (2 * HH + uc);

    for (int t = j; t < TT; t += NTHREADS) xcol[t] = x[t * BB + (BB - 1)];
    if (j < 56) { h_s[0][j] = 0.0f; h_s[1][j] = 0.0f; }

    // Two weight rows per thread, packed f32x2 (row byte offset j*200, 8B aligned)
    ull wpA[25], wpB[25];
    {
        const ull* ra = reinterpret_cast<const ull*>(W_hh + rowA * HH);
        const ull* rb = reinterpret_cast<const ull*>(W_hh + rowB * HH);
        #pragma unroll
        for (int k = 0; k < 25; k++) { wpA[k] = ra[k]; wpB[k] = rb[k]; }
    }
    const float bsumA = b_ih[rowA] + b_hh[rowA];
    const float bsumB = b_ih[rowB] + b_hh[rowB];
    const float wihA  = W_ih[rowA];
    const float wihB  = W_ih[rowB];
    // activation constants for rowB: tanh (even) vs sigmoid (odd)
    const float ascB  = half ? 0.5f : 1.0f;
    const float amulB = half ? 0.5f : 1.0f;
    const float aaddB = half ? 0.5f : 0.0f;

    float c = 0.0f;                 // live on odd lanes only
    __syncthreads();

    #pragma unroll 1
    for (int t2 = 0; t2 < TT; t2 += 2) {
        #pragma unroll
        for (int s = 0; s < 2; s++) {
            const int t = t2 + s;
            const float* hsrc = h_s[s];
            float*       hdst = h_s[s ^ 1];
            const float  xv   = xcol[t];
            const float preA0 = fmaf(xv, wihA, bsumA);
            const float preB0 = fmaf(xv, wihB, bsumB);

            // --- two 50-dots sharing one h load (12 LDS.128 + 1 LDS.64) ---
            ull aA0 = 0ull, aA1 = 0ull, aB0 = 0ull, aB1 = 0ull;
            const ulonglong2* h4 = reinterpret_cast<const ulonglong2*>(hsrc);
            #pragma unroll
            for (int k = 0; k < 12; k++) {
                ulonglong2 p = h4[k];
                aA0 = ffma2(wpA[2 * k],     p.x, aA0);
                aA1 = ffma2(wpA[2 * k + 1], p.y, aA1);
                aB0 = ffma2(wpB[2 * k],     p.x, aB0);
                aB1 = ffma2(wpB[2 * k + 1], p.y, aB1);
            }
            {
                ull hl = reinterpret_cast<const ull*>(hsrc)[24];
                aA0 = ffma2(wpA[24], hl, aA0);
                aB0 = ffma2(wpB[24], hl, aB0);
            }
            union { ull uv; float2 f; } uA0, uA1, uB0, uB1;
            uA0.uv = aA0; uA1.uv = aA1; uB0.uv = aB0; uB1.uv = aB1;
            float preA = preA0 + ((uA0.f.x + uA1.f.x) + (uA0.f.y + uA1.f.y));
            float preB = preB0 + ((uB0.f.x + uB1.f.x) + (uB0.f.y + uB1.f.y));

            // --- activations: sigmoid = 0.5 + 0.5*tanh(x/2) ---
            float aAv = fmaf(tanh_fast(preA * 0.5f), 0.5f, 0.5f);     // i / f
            float aBv = fmaf(tanh_fast(preB * ascB), amulB, aaddB);   // g / o

            // --- SINGLE shuffle: even lane ships p = i*g to its odd partner ---
            float pv  = aAv * aBv;            // meaningful on even lanes
            float got = __shfl_xor_sync(0xffffffffu, pv, 1, 32);

            if (half) {                        // odd lane owns c and h
                c = fmaf(aAv, c, got);         // c = f*c + i*g
                float hn = aBv * tanh_fast(c); // h = o*tanh(c)
                if (u < HH) {
                    hdst[u] = hn;              // critical STS
                    g_hs[t * HH + u] = hn;     // fire-and-forget for epilogue
                }
            }
            __syncthreads();
        }
    }

    // Epilogue: out[t] = dot(h_t, W_lin) + b_lin, parallel over t.
    const float bl = b_lin[0];
    for (int t = j; t < TT; t += NTHREADS) {
        float s = bl;
        #pragma unroll
        for (int k = 0; k < HH; k++) s += g_hs[t * HH + k] * W_lin[k];
        out[t] = s;
    }
}

extern "C" void kernel_launch(void* const* d_in, const int* in_sizes, int n_in,
                              void* d_out, int out_size) {
    const float* x     = (const float*)d_in[0];
    const float* W_ih  = (const float*)d_in[1];
    const float* W_hh  = (const float*)d_in[2];
    const float* b_ih  = (const float*)d_in[3];
    const float* b_hh  = (const float*)d_in[4];
    const float* W_lin = (const float*)d_in[5];
    const float* b_lin = (const float*)d_in[6];
    lstm_seq_kernel<<<1, NTHREADS>>>(x, W_ih, W_hh, b_ih, b_hh, W_lin, b_lin,
                                     (float*)d_out);
}